// round 15
// baseline (speedup 1.0000x reference)
#include <cuda_runtime.h>

// Rotation_agg: out[n, :] = mean_l ( cmul(feat[n,l,:], finals[l,:]) ), finals[3]=identity.
// Converged HBM-bound stream (1.28 GB minimal traffic, ~7.15 TB/s = 90% of spec).
// R14: Blackwell 256-bit vector loads/stores (ld.global.nc.v8.f32) — one instruction per
// layer per thread (2 float4 columns), dense 1KB warp spans, half the LDG/STG count.

#define ROT_EPS 1e-12f

__device__ __forceinline__ void ldg256(const float* p, float4& a, float4& b) {
    asm volatile("ld.global.nc.v8.f32 {%0,%1,%2,%3,%4,%5,%6,%7}, [%8];"
                 : "=f"(a.x), "=f"(a.y), "=f"(a.z), "=f"(a.w),
                   "=f"(b.x), "=f"(b.y), "=f"(b.z), "=f"(b.w)
                 : "l"(p));
}

__device__ __forceinline__ void stg256(float* p, const float4& a, const float4& b) {
    asm volatile("st.global.v8.f32 [%0], {%1,%2,%3,%4,%5,%6,%7,%8};"
                 :: "l"(p),
                    "f"(a.x), "f"(a.y), "f"(a.z), "f"(a.w),
                    "f"(b.x), "f"(b.y), "f"(b.z), "f"(b.w)
                 : "memory");
}

__global__ __launch_bounds__(256) void rotation_agg_kernel(
    const float* __restrict__ feat,
    const float* __restrict__ r_vec,
    float* __restrict__ out,
    int total32)   // N*8 work items (one per 32B pair-column)
{
    __shared__ float2 sf[3][32];   // finals for l=0,1,2 per complex index k

    const int tid = threadIdx.x;
    if (tid < 32) {
        const int k = tid;
        float2 rn[3];
#pragma unroll
        for (int e = 0; e < 3; e++) {
            float x = r_vec[e * 64 + k * 2 + 0];
            float y = r_vec[e * 64 + k * 2 + 1];
            float nrm = sqrtf(x * x + y * y);
            float inv = 1.0f / fmaxf(nrm, ROT_EPS);
            rn[e] = make_float2(x * inv, y * inv);
        }
        float2 f2 = make_float2(rn[2].x, -rn[2].y);               // conj(rn2)
        float2 c1 = make_float2(rn[1].x, -rn[1].y);               // conj(rn1)
        float2 f1 = make_float2(f2.x * c1.x - f2.y * c1.y,
                                f2.x * c1.y + f2.y * c1.x);       // f2 * conj(rn1)
        float2 f0 = make_float2(f1.x * rn[0].x - f1.y * rn[0].y,
                                f1.x * rn[0].y + f1.y * rn[0].x); // f1 * rn0
        sf[0][k] = f0;
        sf[1][k] = f1;
        sf[2][k] = f2;
    }
    __syncthreads();

    const int t = blockIdx.x * 256 + tid;
    if (t >= total32) return;

    const int n = t >> 3;
    const int p = t & 7;                 // pair-column -> complex indices 4p..4p+3

    const float* base = feat + (long long)n * 256 + p * 8;

    // 4 x 256-bit loads (one per layer), each a dense 32B per thread / 1KB per warp-octet.
    float4 a0, b0, a1, b1, a2, b2, a3, b3;
    ldg256(base +   0, a0, b0);
    ldg256(base +  64, a1, b1);
    ldg256(base + 128, a2, b2);
    ldg256(base + 192, a3, b3);

    const float2 fA0 = sf[0][4 * p],     fA1 = sf[0][4 * p + 1];
    const float2 fA2 = sf[0][4 * p + 2], fA3 = sf[0][4 * p + 3];
    const float2 fB0 = sf[1][4 * p],     fB1 = sf[1][4 * p + 1];
    const float2 fB2 = sf[1][4 * p + 2], fB3 = sf[1][4 * p + 3];
    const float2 fC0 = sf[2][4 * p],     fC1 = sf[2][4 * p + 1];
    const float2 fC2 = sf[2][4 * p + 2], fC3 = sf[2][4 * p + 3];

    float4 accA, accB;
    accA.x = a3.x + (a0.x * fA0.x - a0.y * fA0.y)
                  + (a1.x * fB0.x - a1.y * fB0.y)
                  + (a2.x * fC0.x - a2.y * fC0.y);
    accA.y = a3.y + (a0.x * fA0.y + a0.y * fA0.x)
                  + (a1.x * fB0.y + a1.y * fB0.x)
                  + (a2.x * fC0.y + a2.y * fC0.x);
    accA.z = a3.z + (a0.z * fA1.x - a0.w * fA1.y)
                  + (a1.z * fB1.x - a1.w * fB1.y)
                  + (a2.z * fC1.x - a2.w * fC1.y);
    accA.w = a3.w + (a0.z * fA1.y + a0.w * fA1.x)
                  + (a1.z * fB1.y + a1.w * fB1.x)
                  + (a2.z * fC1.y + a2.w * fC1.x);

    accB.x = b3.x + (b0.x * fA2.x - b0.y * fA2.y)
                  + (b1.x * fB2.x - b1.y * fB2.y)
                  + (b2.x * fC2.x - b2.y * fC2.y);
    accB.y = b3.y + (b0.x * fA2.y + b0.y * fA2.x)
                  + (b1.x * fB2.y + b1.y * fB2.x)
                  + (b2.x * fC2.y + b2.y * fC2.x);
    accB.z = b3.z + (b0.z * fA3.x - b0.w * fA3.y)
                  + (b1.z * fB3.x - b1.w * fB3.y)
                  + (b2.z * fC3.x - b2.w * fC3.y);
    accB.w = b3.w + (b0.z * fA3.y + b0.w * fA3.x)
                  + (b1.z * fB3.y + b1.w * fB3.x)
                  + (b2.z * fC3.y + b2.w * fC3.x);

    accA.x *= 0.25f; accA.y *= 0.25f; accA.z *= 0.25f; accA.w *= 0.25f;
    accB.x *= 0.25f; accB.y *= 0.25f; accB.z *= 0.25f; accB.w *= 0.25f;

    stg256(out + (long long)n * 64 + p * 8, accA, accB);
}

extern "C" void kernel_launch(void* const* d_in, const int* in_sizes, int n_in,
                              void* d_out, int out_size)
{
    const float* feat  = (const float*)d_in[0];   // (N, 4, 64) fp32
    const float* r_vec = (const float*)d_in[1];   // (4, 32, 2) fp32
    float* out = (float*)d_out;                   // (N, 64) fp32

    const int N = in_sizes[0] / 256;              // 4*64 floats per row
    const int total = N * 8;                      // 32B pair-column work items
    const int threads = 256;
    const int blocks = (total + threads - 1) / threads;

    rotation_agg_kernel<<<blocks, threads>>>(feat, r_vec, out, total);
}

// round 16
// speedup vs baseline: 1.0330x; 1.0330x over previous
#include <cuda_runtime.h>

// Rotation_agg — FINAL, converged at the HBM roofline.
// out[n, :] = mean_l ( cmul(feat[n,l,:], finals[l,:]) ), finals[3]=identity.
// Traffic is provably minimal (1.024 GB read + 256 MB write = 1.28 GB); kernel streams at
// 7.1-7.2 TB/s = ~90% of HBM3e spec, invariant across 10 structural variants
// (cache hints, L2::256B, tile shapes, persistence, split launches, block sizes, v8 ops).
// Best measured config: 1 float4/thread, flat grid, 4 batched LDG.128 (MLP=4),
// evict-first streaming policy, 32 regs, 256-thread blocks. Bench: 178.27us.

#define ROT_EPS 1e-12f

__global__ __launch_bounds__(256) void rotation_agg_kernel(
    const float* __restrict__ feat,
    const float* __restrict__ r_vec,
    float* __restrict__ out,
    int total32)   // N*16 work items
{
    __shared__ float2 sf[3][32];   // finals for l=0,1,2 per complex index k

    const int tid = threadIdx.x;
    if (tid < 32) {
        const int k = tid;
        float2 rn[3];
#pragma unroll
        for (int e = 0; e < 3; e++) {
            float x = r_vec[e * 64 + k * 2 + 0];
            float y = r_vec[e * 64 + k * 2 + 1];
            float nrm = sqrtf(x * x + y * y);
            float inv = 1.0f / fmaxf(nrm, ROT_EPS);
            rn[e] = make_float2(x * inv, y * inv);
        }
        float2 f2 = make_float2(rn[2].x, -rn[2].y);               // conj(rn2)
        float2 c1 = make_float2(rn[1].x, -rn[1].y);               // conj(rn1)
        float2 f1 = make_float2(f2.x * c1.x - f2.y * c1.y,
                                f2.x * c1.y + f2.y * c1.x);       // f2 * conj(rn1)
        float2 f0 = make_float2(f1.x * rn[0].x - f1.y * rn[0].y,
                                f1.x * rn[0].y + f1.y * rn[0].x); // f1 * rn0
        sf[0][k] = f0;
        sf[1][k] = f1;
        sf[2][k] = f2;
    }
    __syncthreads();

    const int t = blockIdx.x * 256 + tid;
    if (t >= total32) return;

    const int n = t >> 4;
    const int c = t & 15;                        // float4 column -> complex pairs 2c, 2c+1

    const float4* in4 = (const float4*)feat + (long long)n * 64 + c;  // 64 float4 per n

    // Batch all 4 layer loads up front (MLP=4); evict-first streaming policy.
    float4 v0 = __ldcs(in4 + 0);
    float4 v1 = __ldcs(in4 + 16);
    float4 v2 = __ldcs(in4 + 32);
    float4 v3 = __ldcs(in4 + 48);

    const float2 f00 = sf[0][2 * c], f01 = sf[0][2 * c + 1];
    const float2 f10 = sf[1][2 * c], f11 = sf[1][2 * c + 1];
    const float2 f20 = sf[2][2 * c], f21 = sf[2][2 * c + 1];

    float4 acc;
    acc.x = v3.x + (v0.x * f00.x - v0.y * f00.y)
                 + (v1.x * f10.x - v1.y * f10.y)
                 + (v2.x * f20.x - v2.y * f20.y);
    acc.y = v3.y + (v0.x * f00.y + v0.y * f00.x)
                 + (v1.x * f10.y + v1.y * f10.x)
                 + (v2.x * f20.y + v2.y * f20.x);
    acc.z = v3.z + (v0.z * f01.x - v0.w * f01.y)
                 + (v1.z * f11.x - v1.w * f11.y)
                 + (v2.z * f21.x - v2.w * f21.y);
    acc.w = v3.w + (v0.z * f01.y + v0.w * f01.x)
                 + (v1.z * f11.y + v1.w * f11.x)
                 + (v2.z * f21.y + v2.w * f21.x);

    acc.x *= 0.25f; acc.y *= 0.25f; acc.z *= 0.25f; acc.w *= 0.25f;

    __stcs((float4*)out + (long long)n * 16 + c, acc);
}

extern "C" void kernel_launch(void* const* d_in, const int* in_sizes, int n_in,
                              void* d_out, int out_size)
{
    const float* feat  = (const float*)d_in[0];   // (N, 4, 64) fp32
    const float* r_vec = (const float*)d_in[1];   // (4, 32, 2) fp32
    float* out = (float*)d_out;                   // (N, 64) fp32

    const int N = in_sizes[0] / 256;              // 4*64 floats per row
    const int total = N * 16;                     // float4 work items
    const int threads = 256;
    const int blocks = (total + threads - 1) / threads;

    rotation_agg_kernel<<<blocks, threads>>>(feat, r_vec, out, total);
}

// round 17
// speedup vs baseline: 1.0335x; 1.0005x over previous
#include <cuda_runtime.h>

// Rotation_agg — converged at the HBM roofline.
// out[n, :] = mean_l ( cmul(feat[n,l,:], finals[l,:]) ), finals[3]=identity.
// Traffic provably minimal (1.024 GB read + 256 MB write); streams at 7.05-7.20 TB/s
// (~88-91% of HBM3e spec) invariant across 11 structural variants. Final sweep point:
// 1024-thread blocks to amortize the per-block coeff prologue 4x vs 256 while keeping
// the byte-identical coalesced access pattern (1 float4/thread, 4 batched LDG.128).

#define ROT_EPS 1e-12f

__global__ __launch_bounds__(1024) void rotation_agg_kernel(
    const float* __restrict__ feat,
    const float* __restrict__ r_vec,
    float* __restrict__ out,
    int total32)   // N*16 work items
{
    __shared__ float2 sf[3][32];   // finals for l=0,1,2 per complex index k

    const int tid = threadIdx.x;
    if (tid < 32) {
        const int k = tid;
        float2 rn[3];
#pragma unroll
        for (int e = 0; e < 3; e++) {
            float x = r_vec[e * 64 + k * 2 + 0];
            float y = r_vec[e * 64 + k * 2 + 1];
            float nrm = sqrtf(x * x + y * y);
            float inv = 1.0f / fmaxf(nrm, ROT_EPS);
            rn[e] = make_float2(x * inv, y * inv);
        }
        float2 f2 = make_float2(rn[2].x, -rn[2].y);               // conj(rn2)
        float2 c1 = make_float2(rn[1].x, -rn[1].y);               // conj(rn1)
        float2 f1 = make_float2(f2.x * c1.x - f2.y * c1.y,
                                f2.x * c1.y + f2.y * c1.x);       // f2 * conj(rn1)
        float2 f0 = make_float2(f1.x * rn[0].x - f1.y * rn[0].y,
                                f1.x * rn[0].y + f1.y * rn[0].x); // f1 * rn0
        sf[0][k] = f0;
        sf[1][k] = f1;
        sf[2][k] = f2;
    }
    __syncthreads();

    const int t = blockIdx.x * 1024 + tid;
    if (t >= total32) return;

    const int n = t >> 4;
    const int c = t & 15;                        // float4 column -> complex pairs 2c, 2c+1

    const float4* in4 = (const float4*)feat + (long long)n * 64 + c;  // 64 float4 per n

    // Batch all 4 layer loads up front (MLP=4); evict-first streaming policy.
    float4 v0 = __ldcs(in4 + 0);
    float4 v1 = __ldcs(in4 + 16);
    float4 v2 = __ldcs(in4 + 32);
    float4 v3 = __ldcs(in4 + 48);

    const float2 f00 = sf[0][2 * c], f01 = sf[0][2 * c + 1];
    const float2 f10 = sf[1][2 * c], f11 = sf[1][2 * c + 1];
    const float2 f20 = sf[2][2 * c], f21 = sf[2][2 * c + 1];

    float4 acc;
    acc.x = v3.x + (v0.x * f00.x - v0.y * f00.y)
                 + (v1.x * f10.x - v1.y * f10.y)
                 + (v2.x * f20.x - v2.y * f20.y);
    acc.y = v3.y + (v0.x * f00.y + v0.y * f00.x)
                 + (v1.x * f10.y + v1.y * f10.x)
                 + (v2.x * f20.y + v2.y * f20.x);
    acc.z = v3.z + (v0.z * f01.x - v0.w * f01.y)
                 + (v1.z * f11.x - v1.w * f11.y)
                 + (v2.z * f21.x - v2.w * f21.y);
    acc.w = v3.w + (v0.z * f01.y + v0.w * f01.x)
                 + (v1.z * f11.y + v1.w * f11.x)
                 + (v2.z * f21.y + v2.w * f21.x);

    acc.x *= 0.25f; acc.y *= 0.25f; acc.z *= 0.25f; acc.w *= 0.25f;

    __stcs((float4*)out + (long long)n * 16 + c, acc);
}

extern "C" void kernel_launch(void* const* d_in, const int* in_sizes, int n_in,
                              void* d_out, int out_size)
{
    const float* feat  = (const float*)d_in[0];   // (N, 4, 64) fp32
    const float* r_vec = (const float*)d_in[1];   // (4, 32, 2) fp32
    float* out = (float*)d_out;                   // (N, 64) fp32

    const int N = in_sizes[0] / 256;              // 4*64 floats per row
    const int total = N * 16;                     // float4 work items
    const int threads = 1024;
    const int blocks = (total + threads - 1) / threads;

    rotation_agg_kernel<<<blocks, threads>>>(feat, r_vec, out, total);
}